// round 15
// baseline (speedup 1.0000x reference)
#include <cuda_runtime.h>
#include <cuda_fp16.h>
#include <math.h>

#define NN 50000
#define EE 800000
#define DIN 96
#define DD 128
#define BB 512
#define NBLK 196   // ceil(NN/256)

// ---------------- device scratch ----------------
__device__ __half g_h[2u * NN * DD];       // ping-pong node features, fp16 (25.6MB)
__device__ float g_invdeg[NN];
__device__ int   g_degi[NN];               // histogram, then cursor
__device__ int   g_ptr[NN + 1];            // CSR row ptr (by dst)
__device__ int   g_csr_src[EE];            // CSR col = src node
__device__ int   g_edges[2 * EE];          // int32-converted edge_index
__device__ int   g_batch[NN];              // int32-converted batch
__device__ int   g_gptr[BB + 1];           // graph boundaries in sorted batch
__device__ float g_ebuf[NN];               // attention logits / weights
__device__ float g_qstar[BB * 2 * DD];
__device__ float g_hh[BB * DD];
__device__ float g_cc[BB * DD];
__device__ float g_gates[BB * 4 * DD];
__device__ int   g_flag[2];                // 1 if the input index array is int64
__device__ int   g_bsum[NBLK];             // per-block degree sums
__device__ int   g_boff[NBLK];             // exclusive scan of block sums
__device__ int   g_dhist[256];             // degree-bucket histogram (descending key)
__device__ int   g_doff[256];              // exclusive scan of buckets
__device__ int   g_dcur[256];              // bucket cursors
__device__ int   g_order[NN];              // degree-sorted node order for MPNN

// ---------------- packed f32x2 helpers (Blackwell FFMA2) ----------------
__device__ __forceinline__ void ffma2(unsigned long long& acc,
                                      unsigned long long a,
                                      unsigned long long b) {
    asm("fma.rn.f32x2 %0, %1, %2, %0;" : "+l"(acc) : "l"(a), "l"(b));
}
__device__ __forceinline__ unsigned long long pk2(float lo, float hi) {
    unsigned long long r;
    asm("mov.b64 %0, {%1, %2};" : "=l"(r) : "f"(lo), "f"(hi));
    return r;
}
__device__ __forceinline__ float upk_sum(unsigned long long v) {
    float lo, hi;
    asm("mov.b64 {%0, %1}, %2;" : "=f"(lo), "=f"(hi) : "l"(v));
    return lo + hi;
}

// ---------------- detect dtypes + zero histograms (grid NBLK) ----------------
__global__ void __launch_bounds__(256) k_detect(const unsigned int* ei,
                                                const unsigned int* bt) {
    int gi = blockIdx.x * 256 + threadIdx.x;
    if (gi < NN) g_degi[gi] = 0;
    if (blockIdx.x == 1) {
        g_dhist[threadIdx.x] = 0;
        g_dcur[threadIdx.x] = 0;
    }
    if (blockIdx.x == 0 && threadIdx.x < 64) {
        int warp = threadIdx.x >> 5, lane = threadIdx.x & 31;
        const unsigned int* buf = warp == 0 ? ei : bt;
        int off = warp == 0 ? 0 : 20000;
        int bad = 0;
        for (int i = lane; i < 512; i += 32)
            if (buf[2 * (off + i) + 1] != 0u) bad = 1;
        unsigned m = __ballot_sync(0xffffffffu, bad);
        if (lane == 0) g_flag[warp] = (m == 0u) ? 1 : 0;
    }
}

// convert + degree histogram fused (dst entries atomicAdd as they convert)
__global__ void k_convert(const void* ei, const void* bt) {
    int i = blockIdx.x * blockDim.x + threadIdx.x;
    if (i < 2 * EE) {
        int v = g_flag[0] ? (int)((const long long*)ei)[i]
                          : ((const int*)ei)[i];
        g_edges[i] = v;
        if (i >= EE) atomicAdd(&g_degi[v], 1);   // dst histogram
    } else if (i < 2 * EE + NN) {
        int j = i - 2 * EE;
        g_batch[j] = g_flag[1] ? (int)((const long long*)bt)[j]
                               : ((const int*)bt)[j];
    }
}

// ---------------- CSR prefix scan (3-phase, device-wide) ----------------
__global__ void __launch_bounds__(256) k_bsum() {
    __shared__ int ws[8];
    int i = blockIdx.x * 256 + threadIdx.x;
    int d = (i < NN) ? g_degi[i] : 0;
    int lane = threadIdx.x & 31, warp = threadIdx.x >> 5;
    int s = d;
#pragma unroll
    for (int o = 16; o; o >>= 1) s += __shfl_xor_sync(0xffffffffu, s, o);
    if (lane == 0) ws[warp] = s;
    __syncthreads();
    if (threadIdx.x == 0) {
        int t = 0;
#pragma unroll
        for (int w = 0; w < 8; w++) t += ws[w];
        g_bsum[blockIdx.x] = t;
    }
}

__global__ void __launch_bounds__(256) k_bscan() {
    __shared__ int sh[256];
    int t = threadIdx.x;
    int v = (t < NBLK) ? g_bsum[t] : 0;
    sh[t] = v;
    __syncthreads();
#pragma unroll
    for (int o = 1; o < 256; o <<= 1) {
        int u = (t >= o) ? sh[t - o] : 0;
        __syncthreads();
        sh[t] += u;
        __syncthreads();
    }
    if (t < NBLK) g_boff[t] = sh[t] - v;
    if (t == NBLK - 1) g_ptr[NN] = sh[t];
}

// phase C: per-node prefix + invdeg + cursor + degree-bucket histogram
__global__ void __launch_bounds__(256) k_pscan() {
    __shared__ int sh[256];
    int i = blockIdx.x * 256 + threadIdx.x;
    int t = threadIdx.x;
    int d = (i < NN) ? g_degi[i] : 0;
    sh[t] = d;
    __syncthreads();
#pragma unroll
    for (int o = 1; o < 256; o <<= 1) {
        int u = (t >= o) ? sh[t - o] : 0;
        __syncthreads();
        sh[t] += u;
        __syncthreads();
    }
    if (i < NN) {
        int p = g_boff[blockIdx.x] + sh[t] - d;
        g_ptr[i] = p;
        g_degi[i] = p;                             // scatter cursor
        g_invdeg[i] = 1.0f / (float)(d > 0 ? d : 1);
        int key = 255 - (d > 255 ? 255 : d);       // descending degree
        atomicAdd(&g_dhist[key], 1);
    }
}

// exclusive scan of the 256 degree buckets
__global__ void __launch_bounds__(256) k_dscan() {
    __shared__ int sh[256];
    int t = threadIdx.x;
    int v = g_dhist[t];
    sh[t] = v;
    __syncthreads();
#pragma unroll
    for (int o = 1; o < 256; o <<= 1) {
        int u = (t >= o) ? sh[t - o] : 0;
        __syncthreads();
        sh[t] += u;
        __syncthreads();
    }
    g_doff[t] = sh[t] - v;
}

// edge scatter + node-order scatter + Set2Set prep (all fused; 800K threads)
__global__ void k_scatter() {
    int i = blockIdx.x * blockDim.x + threadIdx.x;
    if (i < EE) {
        int d = g_edges[EE + i];
        int slot = atomicAdd(&g_degi[d], 1);
        g_csr_src[slot] = g_edges[i];
    }
    if (i < NN) {
        int d = g_ptr[i + 1] - g_ptr[i];
        int key = 255 - (d > 255 ? 255 : d);
        int slot = g_doff[key] + atomicAdd(&g_dcur[key], 1);
        g_order[slot] = i;
        // graph boundaries from sorted batch
        int b = g_batch[i];
        if (i == 0) {
            for (int t = 0; t <= b; t++) g_gptr[t] = 0;
        } else {
            int p = g_batch[i - 1];
            for (int t = p + 1; t <= b; t++) g_gptr[t] = i;
        }
        if (i == NN - 1) {
            for (int t = b + 1; t <= BB; t++) g_gptr[t] = NN;
        }
    }
    if (i < BB * 2 * DD) g_qstar[i] = 0.f;
    if (i < BB * DD) { g_hh[i] = 0.f; g_cc[i] = 0.f; }
}

// ---------------- input layer: h = relu(x @ W_in^T + b_in), fp16 out ----------------
__global__ void __launch_bounds__(128) k_input(const float* __restrict__ x,
                                               const float* __restrict__ W,
                                               const float* __restrict__ bias) {
    __shared__ __align__(16) float wst[128][34];
    __shared__ __align__(16) float xs[16][96];
    int tid = threadIdx.x;
    unsigned long long w2[48];
#pragma unroll
    for (int c = 0; c < 3; c++) {
        for (int idx = tid; idx < 128 * 32; idx += 128) {
            int d = idx >> 5, kk = idx & 31;
            wst[d][kk] = W[d * 96 + c * 32 + kk];
        }
        __syncthreads();
#pragma unroll
        for (int k2 = 0; k2 < 16; k2++)
            w2[c * 16 + k2] = *(const unsigned long long*)&wst[tid][k2 * 2];
        __syncthreads();
    }
    float bv = bias[tid];
    int nb = blockIdx.x * 16;
    for (int idx = tid; idx < 16 * 96; idx += 128) {
        int n = idx / 96, k = idx % 96;
        xs[n][k] = x[(size_t)(nb + n) * 96 + k];
    }
    __syncthreads();
#pragma unroll
    for (int j4 = 0; j4 < 4; j4++) {
        unsigned long long a0 = pk2(bv, 0.f), a1 = pk2(bv, 0.f);
        unsigned long long a2 = pk2(bv, 0.f), a3 = pk2(bv, 0.f);
#pragma unroll
        for (int k4 = 0; k4 < 24; k4++) {
            ulonglong2 x0 = *(const ulonglong2*)&xs[j4 * 4 + 0][k4 * 4];
            ulonglong2 x1 = *(const ulonglong2*)&xs[j4 * 4 + 1][k4 * 4];
            ulonglong2 x2 = *(const ulonglong2*)&xs[j4 * 4 + 2][k4 * 4];
            ulonglong2 x3 = *(const ulonglong2*)&xs[j4 * 4 + 3][k4 * 4];
            unsigned long long wa = w2[2 * k4], wb = w2[2 * k4 + 1];
            ffma2(a0, x0.x, wa); ffma2(a0, x0.y, wb);
            ffma2(a1, x1.x, wa); ffma2(a1, x1.y, wb);
            ffma2(a2, x2.x, wa); ffma2(a2, x2.y, wb);
            ffma2(a3, x3.x, wa); ffma2(a3, x3.y, wb);
        }
        int n0 = nb + j4 * 4;
        g_h[(size_t)(n0 + 0) * DD + tid] = __float2half(fmaxf(upk_sum(a0), 0.f));
        g_h[(size_t)(n0 + 1) * DD + tid] = __float2half(fmaxf(upk_sum(a1), 0.f));
        g_h[(size_t)(n0 + 2) * DD + tid] = __float2half(fmaxf(upk_sum(a2), 0.f));
        g_h[(size_t)(n0 + 3) * DD + tid] = __float2half(fmaxf(upk_sum(a3), 0.f));
    }
}

// ---------------- MPNN step: warp per node (degree-sorted), fp16 gather ----------------
__device__ __forceinline__ void acc4(float& a0, float& a1, float& a2, float& a3,
                                     uint2 v) {
    float2 f0 = __half22float2(*(__half2*)&v.x);
    float2 f1 = __half22float2(*(__half2*)&v.y);
    a0 += f0.x; a1 += f0.y; a2 += f1.x; a3 += f1.y;
}

__global__ void __launch_bounds__(256) k_mpnn(int dir) {
    const __half* __restrict__ hin = g_h + (size_t)(dir & 1) * NN * DD;
    __half* __restrict__ hout = g_h + (size_t)((dir & 1) ^ 1) * NN * DD;
    const int* __restrict__ csr = g_csr_src;
    int w = (blockIdx.x * blockDim.x + threadIdx.x) >> 5;
    if (w >= NN) return;
    int node = g_order[w];                 // degree-sorted schedule
    int lane = threadIdx.x & 31;
    int beg = g_ptr[node], end = g_ptr[node + 1];
    float a0 = 0.f, a1 = 0.f, a2 = 0.f, a3 = 0.f;
    int e = beg;
    for (; e + 8 <= end; e += 8) {
        int s0 = csr[e + 0], s1 = csr[e + 1], s2 = csr[e + 2], s3 = csr[e + 3];
        int s4 = csr[e + 4], s5 = csr[e + 5], s6 = csr[e + 6], s7 = csr[e + 7];
        uint2 v0 = ((const uint2*)(hin + (size_t)s0 * DD))[lane];
        uint2 v1 = ((const uint2*)(hin + (size_t)s1 * DD))[lane];
        uint2 v2 = ((const uint2*)(hin + (size_t)s2 * DD))[lane];
        uint2 v3 = ((const uint2*)(hin + (size_t)s3 * DD))[lane];
        uint2 v4 = ((const uint2*)(hin + (size_t)s4 * DD))[lane];
        uint2 v5 = ((const uint2*)(hin + (size_t)s5 * DD))[lane];
        uint2 v6 = ((const uint2*)(hin + (size_t)s6 * DD))[lane];
        uint2 v7 = ((const uint2*)(hin + (size_t)s7 * DD))[lane];
        acc4(a0, a1, a2, a3, v0); acc4(a0, a1, a2, a3, v1);
        acc4(a0, a1, a2, a3, v2); acc4(a0, a1, a2, a3, v3);
        acc4(a0, a1, a2, a3, v4); acc4(a0, a1, a2, a3, v5);
        acc4(a0, a1, a2, a3, v6); acc4(a0, a1, a2, a3, v7);
    }
    for (; e + 4 <= end; e += 4) {
        int s0 = csr[e + 0], s1 = csr[e + 1], s2 = csr[e + 2], s3 = csr[e + 3];
        uint2 v0 = ((const uint2*)(hin + (size_t)s0 * DD))[lane];
        uint2 v1 = ((const uint2*)(hin + (size_t)s1 * DD))[lane];
        uint2 v2 = ((const uint2*)(hin + (size_t)s2 * DD))[lane];
        uint2 v3 = ((const uint2*)(hin + (size_t)s3 * DD))[lane];
        acc4(a0, a1, a2, a3, v0); acc4(a0, a1, a2, a3, v1);
        acc4(a0, a1, a2, a3, v2); acc4(a0, a1, a2, a3, v3);
    }
    for (; e < end; e++) {
        uint2 v = ((const uint2*)(hin + (size_t)csr[e] * DD))[lane];
        acc4(a0, a1, a2, a3, v);
    }
    uint2 sv = ((const uint2*)(hin + (size_t)node * DD))[lane];
    float2 s0 = __half22float2(*(__half2*)&sv.x);
    float2 s1 = __half22float2(*(__half2*)&sv.y);
    float id = g_invdeg[node];
    float o0 = (s0.x + a0 * id) * 0.5f;
    float o1 = (s0.y + a1 * id) * 0.5f;
    float o2 = (s1.x + a2 * id) * 0.5f;
    float o3 = (s1.y + a3 * id) * 0.5f;
    uint2 ov;
    *(__half2*)&ov.x = __floats2half2_rn(o0, o1);
    *(__half2*)&ov.y = __floats2half2_rn(o2, o3);
    ((uint2*)(hout + (size_t)node * DD))[lane] = ov;
}

// ---------------- gates GEMM: 32x64 tiles, 128 blocks ----------------
__global__ void __launch_bounds__(256) k_gates(const float* __restrict__ Wih,
                                               const float* __restrict__ Whh,
                                               const float* __restrict__ bih,
                                               const float* __restrict__ bhh) {
    __shared__ __align__(16) float as[16][34];
    __shared__ __align__(16) float bs[16][68];
    int tid = threadIdx.x;
    int bx = blockIdx.x & 7, by = blockIdx.x >> 3;
    int tx = tid & 15, ty = tid >> 4;
    int r0 = ty * 2, c0 = tx * 4;
    float acc[2][4];
#pragma unroll
    for (int i = 0; i < 2; i++)
#pragma unroll
        for (int j = 0; j < 4; j++) acc[i][j] = 0.f;

    for (int kb = 0; kb < 256; kb += 16) {
#pragma unroll
        for (int t = 0; t < 2; t++) {
            int idx = tid + t * 256;
            int r = idx >> 4, k = idx & 15;
            as[k][r] = g_qstar[(size_t)(by * 32 + r) * 256 + kb + k];
        }
#pragma unroll
        for (int t = 0; t < 4; t++) {
            int idx = tid + t * 256;
            int r = idx >> 4, k = idx & 15;
            bs[k][r] = Wih[(size_t)(bx * 64 + r) * 256 + kb + k];
        }
        __syncthreads();
#pragma unroll
        for (int k = 0; k < 16; k++) {
            float2 av = *(const float2*)&as[k][r0];
            float4 bv = *(const float4*)&bs[k][c0];
            float a[2] = {av.x, av.y};
            float b[4] = {bv.x, bv.y, bv.z, bv.w};
#pragma unroll
            for (int i = 0; i < 2; i++)
#pragma unroll
                for (int j = 0; j < 4; j++) acc[i][j] += a[i] * b[j];
        }
        __syncthreads();
    }
    for (int kb = 0; kb < 128; kb += 16) {
#pragma unroll
        for (int t = 0; t < 2; t++) {
            int idx = tid + t * 256;
            int r = idx >> 4, k = idx & 15;
            as[k][r] = g_hh[(size_t)(by * 32 + r) * 128 + kb + k];
        }
#pragma unroll
        for (int t = 0; t < 4; t++) {
            int idx = tid + t * 256;
            int r = idx >> 4, k = idx & 15;
            bs[k][r] = Whh[(size_t)(bx * 64 + r) * 128 + kb + k];
        }
        __syncthreads();
#pragma unroll
        for (int k = 0; k < 16; k++) {
            float2 av = *(const float2*)&as[k][r0];
            float4 bv = *(const float4*)&bs[k][c0];
            float a[2] = {av.x, av.y};
            float b[4] = {bv.x, bv.y, bv.z, bv.w};
#pragma unroll
            for (int i = 0; i < 2; i++)
#pragma unroll
                for (int j = 0; j < 4; j++) acc[i][j] += a[i] * b[j];
        }
        __syncthreads();
    }
#pragma unroll
    for (int i = 0; i < 2; i++) {
        int r = by * 32 + r0 + i;
        int c = bx * 64 + c0;
        float4 o;
        o.x = acc[i][0] + bih[c + 0] + bhh[c + 0];
        o.y = acc[i][1] + bih[c + 1] + bhh[c + 1];
        o.z = acc[i][2] + bih[c + 2] + bhh[c + 2];
        o.w = acc[i][3] + bih[c + 3] + bhh[c + 3];
        *(float4*)&g_gates[(size_t)r * 512 + c] = o;
    }
}

// ---------------- fused LSTM + attention + readout (+ pred on last iter) ----------------
__global__ void __launch_bounds__(128) k_attn(const float* __restrict__ Wp,
                                              const float* __restrict__ bp,
                                              float* __restrict__ out, int last) {
    int g = blockIdx.x;
    int beg = g_gptr[g], end = g_gptr[g + 1];
    int tid = threadIdx.x, lane = tid & 31, warp = tid >> 5;
    __shared__ float q[128];
    __shared__ float red[4];
    __shared__ float part[4][128];

    {
        const float* gr = g_gates + (size_t)g * 512;
        float ig = gr[tid], fg = gr[128 + tid], gg = gr[256 + tid], og = gr[384 + tid];
        float c = g_cc[g * 128 + tid];
        float si = 1.f / (1.f + expf(-ig));
        float sf = 1.f / (1.f + expf(-fg));
        float so = 1.f / (1.f + expf(-og));
        c = sf * c + si * tanhf(gg);
        g_cc[g * 128 + tid] = c;
        float h = so * tanhf(c);
        g_hh[g * 128 + tid] = h;
        q[tid] = h;
    }
    __syncthreads();
    float4 qv = ((const float4*)q)[lane];

    float wmax = -3.4e38f;
    for (int n = beg + warp; n < end; n += 4) {
        uint2 hv = ((const uint2*)(g_h + (size_t)n * DD))[lane];
        float2 f0 = __half22float2(*(__half2*)&hv.x);
        float2 f1 = __half22float2(*(__half2*)&hv.y);
        float s = f0.x * qv.x + f0.y * qv.y + f1.x * qv.z + f1.y * qv.w;
#pragma unroll
        for (int o = 16; o; o >>= 1) s += __shfl_xor_sync(0xffffffffu, s, o);
        if (lane == 0) g_ebuf[n] = s;
        wmax = fmaxf(wmax, s);
    }
    if (lane == 0) red[warp] = wmax;
    __syncthreads();
    float m = fmaxf(fmaxf(red[0], red[1]), fmaxf(red[2], red[3]));
    __syncthreads();

    float ls = 0.f;
    for (int n = beg + tid; n < end; n += 128) {
        float a = expf(g_ebuf[n] - m);
        g_ebuf[n] = a;
        ls += a;
    }
#pragma unroll
    for (int o = 16; o; o >>= 1) ls += __shfl_xor_sync(0xffffffffu, ls, o);
    if (lane == 0) red[warp] = ls;
    __syncthreads();
    float asum = red[0] + red[1] + red[2] + red[3];
    float inv = 1.f / (asum + 1e-16f);

    float a0 = 0.f, a1 = 0.f, a2 = 0.f, a3 = 0.f;
    for (int n = beg + warp; n < end; n += 4) {
        float aw = g_ebuf[n];
        uint2 hv = ((const uint2*)(g_h + (size_t)n * DD))[lane];
        float2 f0 = __half22float2(*(__half2*)&hv.x);
        float2 f1 = __half22float2(*(__half2*)&hv.y);
        a0 += aw * f0.x; a1 += aw * f0.y; a2 += aw * f1.x; a3 += aw * f1.y;
    }
    part[warp][lane * 4 + 0] = a0;
    part[warp][lane * 4 + 1] = a1;
    part[warp][lane * 4 + 2] = a2;
    part[warp][lane * 4 + 3] = a3;
    __syncthreads();
    float r = (part[0][tid] + part[1][tid] + part[2][tid] + part[3][tid]) * inv;
    g_qstar[g * 256 + tid]       = q[tid];
    g_qstar[g * 256 + 128 + tid] = r;

    if (last) {
        float s = q[tid] * Wp[tid] + r * Wp[128 + tid];
#pragma unroll
        for (int o = 16; o; o >>= 1) s += __shfl_xor_sync(0xffffffffu, s, o);
        __syncthreads();
        if (lane == 0) red[warp] = s;
        __syncthreads();
        if (tid == 0) out[g] = red[0] + red[1] + red[2] + red[3] + bp[0];
    }
}

// ---------------- orchestration ----------------
extern "C" void kernel_launch(void* const* d_in, const int* in_sizes, int n_in,
                              void* d_out, int out_size) {
    const float* x      = (const float*)d_in[0];
    const void*  ei     = d_in[1];
    const void*  bt     = d_in[2];
    const float* W_in   = (const float*)d_in[3];
    const float* b_in   = (const float*)d_in[4];
    const float* W_ih   = (const float*)d_in[5];
    const float* W_hh   = (const float*)d_in[6];
    const float* b_ih   = (const float*)d_in[7];
    const float* b_hh   = (const float*)d_in[8];
    const float* W_pred = (const float*)d_in[9];
    const float* b_pred = (const float*)d_in[10];
    float* out = (float*)d_out;

    k_detect<<<NBLK, 256>>>((const unsigned int*)ei, (const unsigned int*)bt);
    k_convert<<<(2 * EE + NN + 255) / 256, 256>>>(ei, bt);

    k_bsum<<<NBLK, 256>>>();
    k_bscan<<<1, 256>>>();
    k_pscan<<<NBLK, 256>>>();
    k_dscan<<<1, 256>>>();
    k_scatter<<<(EE + 255) / 256, 256>>>();

    k_input<<<NN / 16, 128>>>(x, W_in, b_in);

    k_mpnn<<<(NN * 32 + 255) / 256, 256>>>(0);
    k_mpnn<<<(NN * 32 + 255) / 256, 256>>>(1);
    k_mpnn<<<(NN * 32 + 255) / 256, 256>>>(0);
    k_mpnn<<<(NN * 32 + 255) / 256, 256>>>(1);

    for (int it = 0; it < 3; it++) {
        k_gates<<<128, 256>>>(W_ih, W_hh, b_ih, b_hh);
        k_attn<<<BB, 128>>>(W_pred, b_pred, out, it == 2);
    }
}

// round 17
// speedup vs baseline: 1.0672x; 1.0672x over previous
#include <cuda_runtime.h>
#include <cuda_fp16.h>
#include <math.h>

#define NN 50000
#define EE 800000
#define DIN 96
#define DD 128
#define BB 512
#define NBLK 196   // ceil(NN/256)

// ---------------- device scratch ----------------
__device__ __half g_h[2u * NN * DD];       // ping-pong node features, fp16 (25.6MB)
__device__ float g_invdeg[NN];
__device__ int   g_degi[NN];               // histogram, then cursor
__device__ int   g_ptr[NN + 1];            // CSR row ptr (by dst)
__device__ int   g_csr_src[EE];            // CSR col = src node
__device__ int   g_edges[2 * EE];          // int32-converted edge_index
__device__ int   g_batch[NN];              // int32-converted batch
__device__ int   g_gptr[BB + 1];           // graph boundaries in sorted batch
__device__ float g_ebuf[NN];               // attention logits / weights
__device__ float g_qstar[BB * 2 * DD];
__device__ float g_hh[BB * DD];
__device__ float g_cc[BB * DD];
__device__ float g_gates[BB * 4 * DD];
__device__ int   g_flag[2];                // 1 if the input index array is int64
__device__ int   g_bsum[NBLK];             // per-block degree sums
__device__ int   g_boff[NBLK];             // exclusive scan of block sums

// ---------------- packed f32x2 helpers (Blackwell FFMA2) ----------------
__device__ __forceinline__ void ffma2(unsigned long long& acc,
                                      unsigned long long a,
                                      unsigned long long b) {
    asm("fma.rn.f32x2 %0, %1, %2, %0;" : "+l"(acc) : "l"(a), "l"(b));
}
__device__ __forceinline__ unsigned long long pk2(float lo, float hi) {
    unsigned long long r;
    asm("mov.b64 %0, {%1, %2};" : "=l"(r) : "f"(lo), "f"(hi));
    return r;
}
__device__ __forceinline__ float upk_sum(unsigned long long v) {
    float lo, hi;
    asm("mov.b64 {%0, %1}, %2;" : "=f"(lo), "=f"(hi) : "l"(v));
    return lo + hi;
}

// ---------------- detect dtypes + zero degree histogram (grid NBLK) ----------------
__global__ void __launch_bounds__(256) k_detect(const unsigned int* ei,
                                                const unsigned int* bt) {
    int gi = blockIdx.x * 256 + threadIdx.x;
    if (gi < NN) g_degi[gi] = 0;
    if (blockIdx.x == 0 && threadIdx.x < 64) {
        int warp = threadIdx.x >> 5, lane = threadIdx.x & 31;
        const unsigned int* buf = warp == 0 ? ei : bt;
        int off = warp == 0 ? 0 : 20000;
        int bad = 0;
        for (int i = lane; i < 512; i += 32)
            if (buf[2 * (off + i) + 1] != 0u) bad = 1;
        unsigned m = __ballot_sync(0xffffffffu, bad);
        if (lane == 0) g_flag[warp] = (m == 0u) ? 1 : 0;
    }
}

// convert + degree histogram fused (dst entries atomicAdd as they convert)
__global__ void k_convert(const void* ei, const void* bt) {
    int i = blockIdx.x * blockDim.x + threadIdx.x;
    if (i < 2 * EE) {
        int v = g_flag[0] ? (int)((const long long*)ei)[i]
                          : ((const int*)ei)[i];
        g_edges[i] = v;
        if (i >= EE) atomicAdd(&g_degi[v], 1);   // dst histogram
    } else if (i < 2 * EE + NN) {
        int j = i - 2 * EE;
        g_batch[j] = g_flag[1] ? (int)((const long long*)bt)[j]
                               : ((const int*)bt)[j];
    }
}

// ---------------- CSR prefix scan (3-phase, device-wide) ----------------
__global__ void __launch_bounds__(256) k_bsum() {
    __shared__ int ws[8];
    int i = blockIdx.x * 256 + threadIdx.x;
    int d = (i < NN) ? g_degi[i] : 0;
    int lane = threadIdx.x & 31, warp = threadIdx.x >> 5;
    int s = d;
#pragma unroll
    for (int o = 16; o; o >>= 1) s += __shfl_xor_sync(0xffffffffu, s, o);
    if (lane == 0) ws[warp] = s;
    __syncthreads();
    if (threadIdx.x == 0) {
        int t = 0;
#pragma unroll
        for (int w = 0; w < 8; w++) t += ws[w];
        g_bsum[blockIdx.x] = t;
    }
}

__global__ void __launch_bounds__(256) k_bscan() {
    __shared__ int sh[256];
    int t = threadIdx.x;
    int v = (t < NBLK) ? g_bsum[t] : 0;
    sh[t] = v;
    __syncthreads();
#pragma unroll
    for (int o = 1; o < 256; o <<= 1) {
        int u = (t >= o) ? sh[t - o] : 0;
        __syncthreads();
        sh[t] += u;
        __syncthreads();
    }
    if (t < NBLK) g_boff[t] = sh[t] - v;
    if (t == NBLK - 1) g_ptr[NN] = sh[t];
}

// phase C: per-node prefix + invdeg + cursor
__global__ void __launch_bounds__(256) k_pscan() {
    __shared__ int sh[256];
    int i = blockIdx.x * 256 + threadIdx.x;
    int t = threadIdx.x;
    int d = (i < NN) ? g_degi[i] : 0;
    sh[t] = d;
    __syncthreads();
#pragma unroll
    for (int o = 1; o < 256; o <<= 1) {
        int u = (t >= o) ? sh[t - o] : 0;
        __syncthreads();
        sh[t] += u;
        __syncthreads();
    }
    if (i < NN) {
        int p = g_boff[blockIdx.x] + sh[t] - d;
        g_ptr[i] = p;
        g_degi[i] = p;                             // scatter cursor
        g_invdeg[i] = 1.0f / (float)(d > 0 ? d : 1);
    }
}

// edge scatter + graph boundaries + Set2Set state init (fused; 800K threads)
__global__ void k_scatter() {
    int i = blockIdx.x * blockDim.x + threadIdx.x;
    if (i < EE) {
        int d = g_edges[EE + i];
        int slot = atomicAdd(&g_degi[d], 1);
        g_csr_src[slot] = g_edges[i];
    }
    if (i < NN) {
        int b = g_batch[i];
        if (i == 0) {
            for (int t = 0; t <= b; t++) g_gptr[t] = 0;
        } else {
            int p = g_batch[i - 1];
            for (int t = p + 1; t <= b; t++) g_gptr[t] = i;
        }
        if (i == NN - 1) {
            for (int t = b + 1; t <= BB; t++) g_gptr[t] = NN;
        }
    }
    if (i < BB * 2 * DD) g_qstar[i] = 0.f;
    if (i < BB * DD) { g_hh[i] = 0.f; g_cc[i] = 0.f; }
}

// ---------------- input layer: h = relu(x @ W_in^T + b_in), fp16 out ----------------
__global__ void __launch_bounds__(128) k_input(const float* __restrict__ x,
                                               const float* __restrict__ W,
                                               const float* __restrict__ bias) {
    __shared__ __align__(16) float wst[128][34];
    __shared__ __align__(16) float xs[16][96];
    int tid = threadIdx.x;
    unsigned long long w2[48];
#pragma unroll
    for (int c = 0; c < 3; c++) {
        for (int idx = tid; idx < 128 * 32; idx += 128) {
            int d = idx >> 5, kk = idx & 31;
            wst[d][kk] = W[d * 96 + c * 32 + kk];
        }
        __syncthreads();
#pragma unroll
        for (int k2 = 0; k2 < 16; k2++)
            w2[c * 16 + k2] = *(const unsigned long long*)&wst[tid][k2 * 2];
        __syncthreads();
    }
    float bv = bias[tid];
    int nb = blockIdx.x * 16;
    for (int idx = tid; idx < 16 * 96; idx += 128) {
        int n = idx / 96, k = idx % 96;
        xs[n][k] = x[(size_t)(nb + n) * 96 + k];
    }
    __syncthreads();
#pragma unroll
    for (int j4 = 0; j4 < 4; j4++) {
        unsigned long long a0 = pk2(bv, 0.f), a1 = pk2(bv, 0.f);
        unsigned long long a2 = pk2(bv, 0.f), a3 = pk2(bv, 0.f);
#pragma unroll
        for (int k4 = 0; k4 < 24; k4++) {
            ulonglong2 x0 = *(const ulonglong2*)&xs[j4 * 4 + 0][k4 * 4];
            ulonglong2 x1 = *(const ulonglong2*)&xs[j4 * 4 + 1][k4 * 4];
            ulonglong2 x2 = *(const ulonglong2*)&xs[j4 * 4 + 2][k4 * 4];
            ulonglong2 x3 = *(const ulonglong2*)&xs[j4 * 4 + 3][k4 * 4];
            unsigned long long wa = w2[2 * k4], wb = w2[2 * k4 + 1];
            ffma2(a0, x0.x, wa); ffma2(a0, x0.y, wb);
            ffma2(a1, x1.x, wa); ffma2(a1, x1.y, wb);
            ffma2(a2, x2.x, wa); ffma2(a2, x2.y, wb);
            ffma2(a3, x3.x, wa); ffma2(a3, x3.y, wb);
        }
        int n0 = nb + j4 * 4;
        g_h[(size_t)(n0 + 0) * DD + tid] = __float2half(fmaxf(upk_sum(a0), 0.f));
        g_h[(size_t)(n0 + 1) * DD + tid] = __float2half(fmaxf(upk_sum(a1), 0.f));
        g_h[(size_t)(n0 + 2) * DD + tid] = __float2half(fmaxf(upk_sum(a2), 0.f));
        g_h[(size_t)(n0 + 3) * DD + tid] = __float2half(fmaxf(upk_sum(a3), 0.f));
    }
}

// ---------------- MPNN step: warp per node (natural order), fp16 gather ----------------
__device__ __forceinline__ void acc4(float& a0, float& a1, float& a2, float& a3,
                                     uint2 v) {
    float2 f0 = __half22float2(*(__half2*)&v.x);
    float2 f1 = __half22float2(*(__half2*)&v.y);
    a0 += f0.x; a1 += f0.y; a2 += f1.x; a3 += f1.y;
}

__global__ void __launch_bounds__(256) k_mpnn(int dir) {
    const __half* __restrict__ hin = g_h + (size_t)(dir & 1) * NN * DD;
    __half* __restrict__ hout = g_h + (size_t)((dir & 1) ^ 1) * NN * DD;
    const int* __restrict__ csr = g_csr_src;
    int w = (blockIdx.x * blockDim.x + threadIdx.x) >> 5;
    if (w >= NN) return;
    int lane = threadIdx.x & 31;
    int beg = g_ptr[w], end = g_ptr[w + 1];
    float a0 = 0.f, a1 = 0.f, a2 = 0.f, a3 = 0.f;
    int e = beg;
    for (; e + 8 <= end; e += 8) {
        int s0 = csr[e + 0], s1 = csr[e + 1], s2 = csr[e + 2], s3 = csr[e + 3];
        int s4 = csr[e + 4], s5 = csr[e + 5], s6 = csr[e + 6], s7 = csr[e + 7];
        uint2 v0 = ((const uint2*)(hin + (size_t)s0 * DD))[lane];
        uint2 v1 = ((const uint2*)(hin + (size_t)s1 * DD))[lane];
        uint2 v2 = ((const uint2*)(hin + (size_t)s2 * DD))[lane];
        uint2 v3 = ((const uint2*)(hin + (size_t)s3 * DD))[lane];
        uint2 v4 = ((const uint2*)(hin + (size_t)s4 * DD))[lane];
        uint2 v5 = ((const uint2*)(hin + (size_t)s5 * DD))[lane];
        uint2 v6 = ((const uint2*)(hin + (size_t)s6 * DD))[lane];
        uint2 v7 = ((const uint2*)(hin + (size_t)s7 * DD))[lane];
        acc4(a0, a1, a2, a3, v0); acc4(a0, a1, a2, a3, v1);
        acc4(a0, a1, a2, a3, v2); acc4(a0, a1, a2, a3, v3);
        acc4(a0, a1, a2, a3, v4); acc4(a0, a1, a2, a3, v5);
        acc4(a0, a1, a2, a3, v6); acc4(a0, a1, a2, a3, v7);
    }
    for (; e + 4 <= end; e += 4) {
        int s0 = csr[e + 0], s1 = csr[e + 1], s2 = csr[e + 2], s3 = csr[e + 3];
        uint2 v0 = ((const uint2*)(hin + (size_t)s0 * DD))[lane];
        uint2 v1 = ((const uint2*)(hin + (size_t)s1 * DD))[lane];
        uint2 v2 = ((const uint2*)(hin + (size_t)s2 * DD))[lane];
        uint2 v3 = ((const uint2*)(hin + (size_t)s3 * DD))[lane];
        acc4(a0, a1, a2, a3, v0); acc4(a0, a1, a2, a3, v1);
        acc4(a0, a1, a2, a3, v2); acc4(a0, a1, a2, a3, v3);
    }
    for (; e < end; e++) {
        uint2 v = ((const uint2*)(hin + (size_t)csr[e] * DD))[lane];
        acc4(a0, a1, a2, a3, v);
    }
    uint2 sv = ((const uint2*)(hin + (size_t)w * DD))[lane];
    float2 s0 = __half22float2(*(__half2*)&sv.x);
    float2 s1 = __half22float2(*(__half2*)&sv.y);
    float id = g_invdeg[w];
    float o0 = (s0.x + a0 * id) * 0.5f;
    float o1 = (s0.y + a1 * id) * 0.5f;
    float o2 = (s1.x + a2 * id) * 0.5f;
    float o3 = (s1.y + a3 * id) * 0.5f;
    uint2 ov;
    *(__half2*)&ov.x = __floats2half2_rn(o0, o1);
    *(__half2*)&ov.y = __floats2half2_rn(o2, o3);
    ((uint2*)(hout + (size_t)w * DD))[lane] = ov;
}

// ---------------- gates GEMM: 32x64 tiles, 128 blocks ----------------
__global__ void __launch_bounds__(256) k_gates(const float* __restrict__ Wih,
                                               const float* __restrict__ Whh,
                                               const float* __restrict__ bih,
                                               const float* __restrict__ bhh) {
    __shared__ __align__(16) float as[16][34];
    __shared__ __align__(16) float bs[16][68];
    int tid = threadIdx.x;
    int bx = blockIdx.x & 7, by = blockIdx.x >> 3;
    int tx = tid & 15, ty = tid >> 4;
    int r0 = ty * 2, c0 = tx * 4;
    float acc[2][4];
#pragma unroll
    for (int i = 0; i < 2; i++)
#pragma unroll
        for (int j = 0; j < 4; j++) acc[i][j] = 0.f;

    for (int kb = 0; kb < 256; kb += 16) {
#pragma unroll
        for (int t = 0; t < 2; t++) {
            int idx = tid + t * 256;
            int r = idx >> 4, k = idx & 15;
            as[k][r] = g_qstar[(size_t)(by * 32 + r) * 256 + kb + k];
        }
#pragma unroll
        for (int t = 0; t < 4; t++) {
            int idx = tid + t * 256;
            int r = idx >> 4, k = idx & 15;
            bs[k][r] = Wih[(size_t)(bx * 64 + r) * 256 + kb + k];
        }
        __syncthreads();
#pragma unroll
        for (int k = 0; k < 16; k++) {
            float2 av = *(const float2*)&as[k][r0];
            float4 bv = *(const float4*)&bs[k][c0];
            float a[2] = {av.x, av.y};
            float b[4] = {bv.x, bv.y, bv.z, bv.w};
#pragma unroll
            for (int i = 0; i < 2; i++)
#pragma unroll
                for (int j = 0; j < 4; j++) acc[i][j] += a[i] * b[j];
        }
        __syncthreads();
    }
    for (int kb = 0; kb < 128; kb += 16) {
#pragma unroll
        for (int t = 0; t < 2; t++) {
            int idx = tid + t * 256;
            int r = idx >> 4, k = idx & 15;
            as[k][r] = g_hh[(size_t)(by * 32 + r) * 128 + kb + k];
        }
#pragma unroll
        for (int t = 0; t < 4; t++) {
            int idx = tid + t * 256;
            int r = idx >> 4, k = idx & 15;
            bs[k][r] = Whh[(size_t)(bx * 64 + r) * 128 + kb + k];
        }
        __syncthreads();
#pragma unroll
        for (int k = 0; k < 16; k++) {
            float2 av = *(const float2*)&as[k][r0];
            float4 bv = *(const float4*)&bs[k][c0];
            float a[2] = {av.x, av.y};
            float b[4] = {bv.x, bv.y, bv.z, bv.w};
#pragma unroll
            for (int i = 0; i < 2; i++)
#pragma unroll
                for (int j = 0; j < 4; j++) acc[i][j] += a[i] * b[j];
        }
        __syncthreads();
    }
#pragma unroll
    for (int i = 0; i < 2; i++) {
        int r = by * 32 + r0 + i;
        int c = bx * 64 + c0;
        float4 o;
        o.x = acc[i][0] + bih[c + 0] + bhh[c + 0];
        o.y = acc[i][1] + bih[c + 1] + bhh[c + 1];
        o.z = acc[i][2] + bih[c + 2] + bhh[c + 2];
        o.w = acc[i][3] + bih[c + 3] + bhh[c + 3];
        *(float4*)&g_gates[(size_t)r * 512 + c] = o;
    }
}

// ---------------- fused LSTM + attention + readout (+ pred on last iter) ----------------
__global__ void __launch_bounds__(128) k_attn(const float* __restrict__ Wp,
                                              const float* __restrict__ bp,
                                              float* __restrict__ out, int last) {
    int g = blockIdx.x;
    int beg = g_gptr[g], end = g_gptr[g + 1];
    int tid = threadIdx.x, lane = tid & 31, warp = tid >> 5;
    __shared__ float q[128];
    __shared__ float red[4];
    __shared__ float part[4][128];

    {
        const float* gr = g_gates + (size_t)g * 512;
        float ig = gr[tid], fg = gr[128 + tid], gg = gr[256 + tid], og = gr[384 + tid];
        float c = g_cc[g * 128 + tid];
        float si = 1.f / (1.f + expf(-ig));
        float sf = 1.f / (1.f + expf(-fg));
        float so = 1.f / (1.f + expf(-og));
        c = sf * c + si * tanhf(gg);
        g_cc[g * 128 + tid] = c;
        float h = so * tanhf(c);
        g_hh[g * 128 + tid] = h;
        q[tid] = h;
    }
    __syncthreads();
    float4 qv = ((const float4*)q)[lane];

    float wmax = -3.4e38f;
    for (int n = beg + warp; n < end; n += 4) {
        uint2 hv = ((const uint2*)(g_h + (size_t)n * DD))[lane];
        float2 f0 = __half22float2(*(__half2*)&hv.x);
        float2 f1 = __half22float2(*(__half2*)&hv.y);
        float s = f0.x * qv.x + f0.y * qv.y + f1.x * qv.z + f1.y * qv.w;
#pragma unroll
        for (int o = 16; o; o >>= 1) s += __shfl_xor_sync(0xffffffffu, s, o);
        if (lane == 0) g_ebuf[n] = s;
        wmax = fmaxf(wmax, s);
    }
    if (lane == 0) red[warp] = wmax;
    __syncthreads();
    float m = fmaxf(fmaxf(red[0], red[1]), fmaxf(red[2], red[3]));
    __syncthreads();

    float ls = 0.f;
    for (int n = beg + tid; n < end; n += 128) {
        float a = expf(g_ebuf[n] - m);
        g_ebuf[n] = a;
        ls += a;
    }
#pragma unroll
    for (int o = 16; o; o >>= 1) ls += __shfl_xor_sync(0xffffffffu, ls, o);
    if (lane == 0) red[warp] = ls;
    __syncthreads();
    float asum = red[0] + red[1] + red[2] + red[3];
    float inv = 1.f / (asum + 1e-16f);

    float a0 = 0.f, a1 = 0.f, a2 = 0.f, a3 = 0.f;
    for (int n = beg + warp; n < end; n += 4) {
        float aw = g_ebuf[n];
        uint2 hv = ((const uint2*)(g_h + (size_t)n * DD))[lane];
        float2 f0 = __half22float2(*(__half2*)&hv.x);
        float2 f1 = __half22float2(*(__half2*)&hv.y);
        a0 += aw * f0.x; a1 += aw * f0.y; a2 += aw * f1.x; a3 += aw * f1.y;
    }
    part[warp][lane * 4 + 0] = a0;
    part[warp][lane * 4 + 1] = a1;
    part[warp][lane * 4 + 2] = a2;
    part[warp][lane * 4 + 3] = a3;
    __syncthreads();
    float r = (part[0][tid] + part[1][tid] + part[2][tid] + part[3][tid]) * inv;
    g_qstar[g * 256 + tid]       = q[tid];
    g_qstar[g * 256 + 128 + tid] = r;

    if (last) {
        float s = q[tid] * Wp[tid] + r * Wp[128 + tid];
#pragma unroll
        for (int o = 16; o; o >>= 1) s += __shfl_xor_sync(0xffffffffu, s, o);
        __syncthreads();
        if (lane == 0) red[warp] = s;
        __syncthreads();
        if (tid == 0) out[g] = red[0] + red[1] + red[2] + red[3] + bp[0];
    }
}

// ---------------- orchestration ----------------
extern "C" void kernel_launch(void* const* d_in, const int* in_sizes, int n_in,
                              void* d_out, int out_size) {
    const float* x      = (const float*)d_in[0];
    const void*  ei     = d_in[1];
    const void*  bt     = d_in[2];
    const float* W_in   = (const float*)d_in[3];
    const float* b_in   = (const float*)d_in[4];
    const float* W_ih   = (const float*)d_in[5];
    const float* W_hh   = (const float*)d_in[6];
    const float* b_ih   = (const float*)d_in[7];
    const float* b_hh   = (const float*)d_in[8];
    const float* W_pred = (const float*)d_in[9];
    const float* b_pred = (const float*)d_in[10];
    float* out = (float*)d_out;

    k_detect<<<NBLK, 256>>>((const unsigned int*)ei, (const unsigned int*)bt);
    k_convert<<<(2 * EE + NN + 255) / 256, 256>>>(ei, bt);

    k_bsum<<<NBLK, 256>>>();
    k_bscan<<<1, 256>>>();
    k_pscan<<<NBLK, 256>>>();
    k_scatter<<<(EE + 255) / 256, 256>>>();

    k_input<<<NN / 16, 128>>>(x, W_in, b_in);

    k_mpnn<<<(NN * 32 + 255) / 256, 256>>>(0);
    k_mpnn<<<(NN * 32 + 255) / 256, 256>>>(1);
    k_mpnn<<<(NN * 32 + 255) / 256, 256>>>(0);
    k_mpnn<<<(NN * 32 + 255) / 256, 256>>>(1);

    for (int it = 0; it < 3; it++) {
        k_gates<<<128, 256>>>(W_ih, W_hh, b_ih, b_hh);
        k_attn<<<BB, 128>>>(W_pred, b_pred, out, it == 2);
    }
}